// round 15
// baseline (speedup 1.0000x reference)
#include <cuda_runtime.h>
#include <math.h>

#define B   16
#define Hh  128
#define Ww  128
#define CI  64
#define CO  64
#define MD  16
#define THETA 0.04908738521234052f   // 2*pi/128

typedef unsigned long long u64;

__device__ __forceinline__ u64 pk(float lo, float hi) {
    u64 r; asm("mov.b64 %0, {%1,%2};" : "=l"(r) : "f"(lo), "f"(hi)); return r;
}
__device__ __forceinline__ u64 fma2(u64 a, u64 b, u64 c) {
    u64 d; asm("fma.rn.f32x2 %0, %1, %2, %3;" : "=l"(d) : "l"(a), "l"(b), "l"(c)); return d;
}
__device__ __forceinline__ u64 add2(u64 a, u64 b) {
    u64 d; asm("add.rn.f32x2 %0, %1, %2;" : "=l"(d) : "l"(a), "l"(b)); return d;
}
#define SGN2 0x8000000080000000ULL

// ---- scratch (device globals; allocation-free). 16B aligned ----
static __device__ __align__(16) float g_Ax[B*MD*Hh*CI];     // [b][kx][h][i]
static __device__ __align__(16) float g_Ay[B*MD*Hh*CI];
static __device__ __align__(16) float g_Xx[MD*MD*B*CI];     // [m][b][i]
static __device__ __align__(16) float g_Xy[MD*MD*B*CI];
static __device__ __align__(16) float g_Wr[MD*MD*CI*CO];    // [m][i*64+o]
static __device__ __align__(16) float g_Wi[MD*MD*CI*CO];
static __device__ __align__(16) float g_Ox[B*MD*MD*CO];     // [b][kx][ky][o]
static __device__ __align__(16) float g_Oy[B*MD*MD*CO];
static __device__ __align__(16) float g_Gx[B*Hh*MD*CO];     // [b][h][kx][o]
static __device__ __align__(16) float g_Gy[B*Hh*MD*CO];

// ============ fused stage A (radix-2, fused twiddle LDS.128) + weight transpose ============
__global__ void __launch_bounds__(256) fusedAT(const float* __restrict__ x,
                                               const float* __restrict__ wr,
                                               const float* __restrict__ wi) {
    __shared__ __align__(16) float pool[8192];       // 32 KB
    __shared__ __align__(16) ulonglong2 sbt[128];    // {(c,c),(s,s)} 2 KB
    int tid = threadIdx.x;

    if (blockIdx.x >= 1024) {
        // ---- weight transpose tile: 32 m x 32 io ----
        int t   = blockIdx.x - 1024;
        int bm  = t & 7;
        int bio = t >> 3;
        int tx  = tid & 31;
        int ty  = tid >> 5;                 // 0..7
        float* sr = pool;                   // [32][33]
        float* si = pool + 1056;
#pragma unroll
        for (int r = 0; r < 4; ++r) {
            int iol = ty + r * 8;
            size_t g = (size_t)(bio * 32 + iol) * 256 + bm * 32 + tx;
            sr[iol * 33 + tx] = wr[g];
            si[iol * 33 + tx] = wi[g];
        }
        __syncthreads();
#pragma unroll
        for (int r = 0; r < 4; ++r) {
            int ml = ty + r * 8;
            size_t dst = (size_t)(bm * 32 + ml) * 4096 + bio * 32 + tx;
            g_Wr[dst] = sr[tx * 33 + ml];
            g_Wi[dst] = si[tx * 33 + ml];
        }
        return;
    }

    // ---- stage A: A[kx] = sum_{w'<64} u_{par(kx)}[w'] e^{-i kx w' th} ----
    if (tid < 128) {
        float s, c;
        sincosf((float)tid * THETA, &s, &c);
        ulonglong2 t;
        t.x = pk(c, c);
        t.y = pk(s, s);
        sbt[tid] = t;
    }
    int b  = blockIdx.x >> 6;
    int hp = blockIdx.x & 63;
    int h0 = hp * 2;
    int ipair = tid & 31, kq = tid >> 5;   // kx = kq, kq+8 (same parity); warp-uniform kq
    int i0 = 2 * ipair;
    int kxa = kq, kxb = kq + 8;
    int du = (kq & 1) * 2048;              // odd kx -> um region
    u64 reA0=0, imA0=0, reB0=0, imB0=0;    // row0: kxa, kxb
    u64 reA1=0, imA1=0, reB1=0, imB1=0;    // row1

    for (int wc = 0; wc < 2; ++wc) {
        __syncthreads();
#pragma unroll
        for (int r = 0; r < 2; ++r) {
            const ulonglong2* src = (const ulonglong2*)(x + ((size_t)(b * Hh + h0 + r) * Ww + wc * 32) * CI);
            ulonglong2* dp = (ulonglong2*)&pool[r * 4096];
            ulonglong2* dm = (ulonglong2*)&pool[r * 4096 + 2048];
            for (int l = tid; l < 512; l += 256) {
                ulonglong2 a = src[l];            // x[w']
                ulonglong2 c = src[l + 1024];     // x[w'+64]
                ulonglong2 p, m;
                p.x = add2(a.x, c.x);         p.y = add2(a.y, c.y);
                m.x = add2(a.x, c.x ^ SGN2);  m.y = add2(a.y, c.y ^ SGN2);
                dp[l] = p;
                dm[l] = m;
            }
        }
        __syncthreads();
        int ida = (kxa * (wc * 32)) & 127;
        int idb = (kxb * (wc * 32)) & 127;
#pragma unroll 8
        for (int wl = 0; wl < 32; ++wl) {
            u64 v0 = *(const u64*)&pool[du + wl * 64 + i0];
            u64 v1 = *(const u64*)&pool[4096 + du + wl * 64 + i0];
            ulonglong2 ta = sbt[ida];
            ulonglong2 tb = sbt[idb];
            ida = (ida + kxa) & 127;
            idb = (idb + kxb) & 127;
            reA0 = fma2(v0, ta.x, reA0);  imA0 = fma2(v0, ta.y, imA0);
            reA1 = fma2(v1, ta.x, reA1);  imA1 = fma2(v1, ta.y, imA1);
            reB0 = fma2(v0, tb.x, reB0);  imB0 = fma2(v0, tb.y, imB0);
            reB1 = fma2(v1, tb.x, reB1);  imB1 = fma2(v1, tb.y, imB1);
        }
    }
    size_t baseA0 = ((size_t)(b * MD + kxa) * Hh + h0    ) * CI;
    size_t baseA1 = ((size_t)(b * MD + kxa) * Hh + h0 + 1) * CI;
    size_t baseB0 = ((size_t)(b * MD + kxb) * Hh + h0    ) * CI;
    size_t baseB1 = ((size_t)(b * MD + kxb) * Hh + h0 + 1) * CI;
    *(u64*)&g_Ax[baseA0 + i0] = reA0;  *(u64*)&g_Ay[baseA0 + i0] = imA0 ^ SGN2;
    *(u64*)&g_Ax[baseA1 + i0] = reA1;  *(u64*)&g_Ay[baseA1 + i0] = imA1 ^ SGN2;
    *(u64*)&g_Ax[baseB0 + i0] = reB0;  *(u64*)&g_Ay[baseB0 + i0] = imB0 ^ SGN2;
    *(u64*)&g_Ax[baseB1 + i0] = reB1;  *(u64*)&g_Ay[baseB1 + i0] = imB1 ^ SGN2;
}

// ============ stage B v4 (radix-2, i-half split): X[m][b][i] = sum_h A e^{-i ky h th} ============
// 512 blocks (b, kx, i-half). 256 thr = 16 ipair x 16 ky.
__global__ void __launch_bounds__(256) stageB() {
    __shared__ __align__(16) float bxp[32 * 32];   // u+ (re) 4 KB
    __shared__ __align__(16) float bxm[32 * 32];   // u- (re)
    __shared__ __align__(16) float byp[32 * 32];   // u+ (im)
    __shared__ __align__(16) float bym[32 * 32];   // u- (im)
    __shared__ __align__(16) ulonglong2 sbt[128];  // {(c,c),(s,s)}
    int b  = blockIdx.x >> 5;
    int kx = (blockIdx.x >> 1) & 15;
    int ic = blockIdx.x & 1;
    int tid = threadIdx.x;
    if (tid < 128) {
        float s, c;
        sincosf((float)tid * THETA, &s, &c);
        ulonglong2 t;
        t.x = pk(c, c);
        t.y = pk(s, s);
        sbt[tid] = t;
    }
    int ipair = tid & 15, ky = tid >> 4;
    int i0 = 2 * ipair;
    int par = ky & 1;
    u64 P = 0, Q = 0, R = 0, S = 0;
    const ulonglong2* Abx = (const ulonglong2*)(g_Ax + (size_t)(b * MD + kx) * Hh * CI);
    const ulonglong2* Aby = (const ulonglong2*)(g_Ay + (size_t)(b * MD + kx) * Hh * CI);

    for (int hc = 0; hc < 2; ++hc) {
        __syncthreads();
        for (int l = tid; l < 256; l += 256) {
            int row = l >> 3, q = l & 7;
            int glo = (hc * 32 + row) * 16 + ic * 8 + q;
            int ghi = (hc * 32 + row + 64) * 16 + ic * 8 + q;
            ulonglong2 ax = Abx[glo], cx = Abx[ghi];
            ulonglong2 ay = Aby[glo], cy = Aby[ghi];
            ulonglong2 t;
            t.x = add2(ax.x, cx.x);        t.y = add2(ax.y, cx.y);
            ((ulonglong2*)bxp)[l] = t;
            t.x = add2(ax.x, cx.x ^ SGN2); t.y = add2(ax.y, cx.y ^ SGN2);
            ((ulonglong2*)bxm)[l] = t;
            t.x = add2(ay.x, cy.x);        t.y = add2(ay.y, cy.y);
            ((ulonglong2*)byp)[l] = t;
            t.x = add2(ay.x, cy.x ^ SGN2); t.y = add2(ay.y, cy.y ^ SGN2);
            ((ulonglong2*)bym)[l] = t;
        }
        __syncthreads();
        const float* bx = par ? bxm : bxp;
        const float* by = par ? bym : byp;
        int idx = (ky * (hc * 32)) & 127;
#pragma unroll 8
        for (int hl = 0; hl < 32; ++hl) {
            u64 ar = *(const u64*)&bx[hl * 32 + i0];
            u64 ai = *(const u64*)&by[hl * 32 + i0];
            ulonglong2 t = sbt[idx];
            idx = (idx + ky) & 127;
            P = fma2(ar, t.x, P);  Q = fma2(ai, t.y, Q);
            R = fma2(ai, t.x, R);  S = fma2(ar, t.y, S);
        }
    }
    // re = P + Q ; im = R - S
    size_t base = ((size_t)(ky * MD + kx) * B + b) * CI + ic * 32;
    *(u64*)&g_Xx[base + i0] = add2(P, Q);
    *(u64*)&g_Xy[base + i0] = add2(R, S ^ SGN2);
}

// ============ stage C v3 (o-half split): O[b][kx][ky][o] = sum_i X[m][b][i]*W[m][i][o] ============
// 512 blocks (m, o-half). 256 thr = 16 o-pair x 16 b.  smem 32 KB.
__global__ void __launch_bounds__(256) stageC() {
    __shared__ __align__(16) float sWr[CI * 32];   // 8 KB
    __shared__ __align__(16) float sWi[CI * 32];   // 8 KB
    __shared__ __align__(16) u64 sXx[B * CI];      // 8 KB ( x, x)
    __shared__ __align__(16) u64 sXn[B * CI];      // 8 KB (-y,-y)
    int m  = blockIdx.x >> 1;
    int oh = blockIdx.x & 1;
    int kx = m & 15, ky = m >> 4;
    int tid = threadIdx.x;
    // weights: rows i (64), cols o in [oh*32, oh*32+32)
    for (int l = tid; l < 512; l += 256) {           // 512 float4 per array
        int i = l >> 3, q = l & 7;
        int gidx = i * 16 + oh * 8 + q;              // float4 units in row of 64
        ((float4*)sWr)[l] = ((const float4*)(g_Wr + (size_t)m * 4096))[gidx];
        ((float4*)sWi)[l] = ((const float4*)(g_Wi + (size_t)m * 4096))[gidx];
    }
    for (int l = tid; l < 1024; l += 256) {
        float vx = g_Xx[m * 1024 + l];
        float vy = g_Xy[m * 1024 + l];
        sXx[l] = pk(vx, vx);
        sXn[l] = pk(-vy, -vy);
    }
    __syncthreads();
    int op = tid & 15;    // o = oh*32 + 2*op
    int b  = tid >> 4;
    u64 P = 0, Q = 0, R = 0, S = 0;
    const u64* xp = &sXx[b * 64];
    const u64* np = &sXn[b * 64];
#pragma unroll 8
    for (int i = 0; i < CI; ++i) {
        u64 wrp = *(const u64*)&sWr[i * 32 + 2 * op];
        u64 wip = *(const u64*)&sWi[i * 32 + 2 * op];
        u64 xv = xp[i], nv = np[i];
        P = fma2(xv, wrp, P);
        Q = fma2(nv, wip, Q);
        R = fma2(xv, wip, R);
        S = fma2(nv, wrp, S);
    }
    size_t base = ((size_t)(b * MD + kx) * MD + ky) * CO + oh * 32 + 2 * op;
    *(u64*)&g_Ox[base] = add2(P, Q);            // re = P + Q
    *(u64*)&g_Oy[base] = add2(R, S ^ SGN2);     // im = R - S
}

// ============ stage D (radix-2, fused twiddle LDS.128): G[h'] = Se+So, G[h'+64] = Se-So ============
__global__ void __launch_bounds__(256, 4) stageD() {
    __shared__ __align__(16) float sOx[MD * CO];
    __shared__ __align__(16) float sOy[MD * CO];
    __shared__ __align__(16) ulonglong2 sT[MD * 32];   // {(c,c),(s,s)} [ky][hl]
    int half = blockIdx.x & 1;
    int kx   = (blockIdx.x >> 1) & 15;
    int b    = blockIdx.x >> 5;
    int hb   = half * 32;                        // h' base (h' < 64)
    int tid  = threadIdx.x;
    for (int l = tid; l < 512; l += 256) {
        int ky = l >> 5, hl = l & 31;
        float s, c;
        sincosf((float)((ky * (hb + hl)) & 127) * THETA, &s, &c);
        ulonglong2 t;
        t.x = pk(c, c);
        t.y = pk(s, s);
        sT[l] = t;
    }
    const float* Osx = g_Ox + (size_t)(b * MD + kx) * MD * CO;
    const float* Osy = g_Oy + (size_t)(b * MD + kx) * MD * CO;
    for (int l = tid; l < 256; l += 256) {
        ((float4*)sOx)[l] = ((const float4*)Osx)[l];
        ((float4*)sOy)[l] = ((const float4*)Osy)[l];
    }
    __syncthreads();

    int oq = tid & 15;    // o = 4*oq (2 pairs)
    int hg = tid >> 4;    // h' = hb + 2*hg + j
    u64 reE[2][2]={{0,0},{0,0}}, imE[2][2]={{0,0},{0,0}};
    u64 reO[2][2]={{0,0},{0,0}}, imO[2][2]={{0,0},{0,0}};
#pragma unroll
    for (int ky = 0; ky < MD; ++ky) {
        ulonglong2 vx = *(const ulonglong2*)&sOx[ky * 64 + 4 * oq];
        ulonglong2 vy = *(const ulonglong2*)&sOy[ky * 64 + 4 * oq];
        u64 vy0n = vy.x ^ SGN2;
        u64 vy1n = vy.y ^ SGN2;
#pragma unroll
        for (int j = 0; j < 2; ++j) {
            int hl = hg * 2 + j;
            ulonglong2 t = sT[ky * 32 + hl];
            u64 cc = t.x, ss = t.y;
            if ((ky & 1) == 0) {
                reE[j][0] = fma2(vx.x, cc, reE[j][0]);  reE[j][0] = fma2(vy0n, ss, reE[j][0]);
                reE[j][1] = fma2(vx.y, cc, reE[j][1]);  reE[j][1] = fma2(vy1n, ss, reE[j][1]);
                imE[j][0] = fma2(vx.x, ss, imE[j][0]);  imE[j][0] = fma2(vy.x, cc, imE[j][0]);
                imE[j][1] = fma2(vx.y, ss, imE[j][1]);  imE[j][1] = fma2(vy.y, cc, imE[j][1]);
            } else {
                reO[j][0] = fma2(vx.x, cc, reO[j][0]);  reO[j][0] = fma2(vy0n, ss, reO[j][0]);
                reO[j][1] = fma2(vx.y, cc, reO[j][1]);  reO[j][1] = fma2(vy1n, ss, reO[j][1]);
                imO[j][0] = fma2(vx.x, ss, imO[j][0]);  imO[j][0] = fma2(vy.x, cc, imO[j][0]);
                imO[j][1] = fma2(vx.y, ss, imO[j][1]);  imO[j][1] = fma2(vy.y, cc, imO[j][1]);
            }
        }
    }
#pragma unroll
    for (int j = 0; j < 2; ++j) {
        int h = hb + hg * 2 + j;
        size_t b0 = ((size_t)(b * Hh + h     ) * MD + kx) * CO + 4 * oq;
        size_t b1 = ((size_t)(b * Hh + h + 64) * MD + kx) * CO + 4 * oq;
        *(u64*)&g_Gx[b0    ] = add2(reE[j][0], reO[j][0]);
        *(u64*)&g_Gx[b0 + 2] = add2(reE[j][1], reO[j][1]);
        *(u64*)&g_Gy[b0    ] = add2(imE[j][0], imO[j][0]);
        *(u64*)&g_Gy[b0 + 2] = add2(imE[j][1], imO[j][1]);
        *(u64*)&g_Gx[b1    ] = add2(reE[j][0], reO[j][0] ^ SGN2);
        *(u64*)&g_Gx[b1 + 2] = add2(reE[j][1], reO[j][1] ^ SGN2);
        *(u64*)&g_Gy[b1    ] = add2(imE[j][0], imO[j][0] ^ SGN2);
        *(u64*)&g_Gy[b1 + 2] = add2(imE[j][1], imO[j][1] ^ SGN2);
    }
}

// ============ stage E (radix-2, 128 threads): y[w'] = Se+So, y[w'+64] = Se-So ============
#define YPAD 66
__global__ void __launch_bounds__(128) stageE(float* __restrict__ y) {
    __shared__ __align__(16) float sGx[MD * CO];
    __shared__ __align__(16) float sGy[MD * CO];
    __shared__ __align__(16) float sY [Ww * YPAD];
    __shared__ __align__(16) u64 sEc[128];
    __shared__ __align__(16) u64 sEs[128];
    int b = blockIdx.x >> 7, h = blockIdx.x & 127;
    int tid = threadIdx.x;
    const float SC = 1.0f / 16384.0f;
    {
        float s, c;
        sincosf((float)tid * THETA, &s, &c);
        sEc[tid] = pk(2.0f * SC * c, 2.0f * SC * c);
        sEs[tid] = pk(-2.0f * SC * s, -2.0f * SC * s);
    }
    const float4* Gxs = (const float4*)&g_Gx[(size_t)(b * Hh + h) * MD * CO];
    const float4* Gys = (const float4*)&g_Gy[(size_t)(b * Hh + h) * MD * CO];
    for (int l = tid; l < MD * CO / 4; l += 128) {
        ((float4*)sGx)[l] = Gxs[l];
        ((float4*)sGy)[l] = Gys[l];
    }
    __syncthreads();
    int wl   = tid & 63;      // w' < 64
    int ohf  = tid >> 6;      // o-half
    u64 tc[16], ts[16];
    tc[0] = pk(SC, SC);  ts[0] = 0;
#pragma unroll
    for (int kx = 1; kx < MD; ++kx) {
        int idx = (kx * wl) & 127;
        tc[kx] = sEc[idx];
        ts[kx] = sEs[idx];
    }

#pragma unroll 2
    for (int oq = 0; oq < 8; ++oq) {
        int oc = (ohf * 8 + oq) * 4;     // o base (4 floats)
        u64 ae01 = 0, ae23 = 0, ao01 = 0, ao23 = 0;
#pragma unroll
        for (int kx = 0; kx < MD; ++kx) {
            ulonglong2 vx = *(const ulonglong2*)&sGx[kx * 64 + oc];
            ulonglong2 vy = *(const ulonglong2*)&sGy[kx * 64 + oc];
            if ((kx & 1) == 0) {
                ae01 = fma2(vx.x, tc[kx], ae01);  ae01 = fma2(vy.x, ts[kx], ae01);
                ae23 = fma2(vx.y, tc[kx], ae23);  ae23 = fma2(vy.y, ts[kx], ae23);
            } else {
                ao01 = fma2(vx.x, tc[kx], ao01);  ao01 = fma2(vy.x, ts[kx], ao01);
                ao23 = fma2(vx.y, tc[kx], ao23);  ao23 = fma2(vy.y, ts[kx], ao23);
            }
        }
        *(u64*)&sY[ wl       * YPAD + oc    ] = add2(ae01, ao01);
        *(u64*)&sY[ wl       * YPAD + oc + 2] = add2(ae23, ao23);
        *(u64*)&sY[(wl + 64) * YPAD + oc    ] = add2(ae01, ao01 ^ SGN2);
        *(u64*)&sY[(wl + 64) * YPAD + oc + 2] = add2(ae23, ao23 ^ SGN2);
    }
    __syncthreads();
    float* yb = y + (size_t)(b * Hh + h) * Ww * CO;
    for (int l = tid; l < Ww * CO / 2; l += 128) {
        int idx = l * 2;
        int ww = idx >> 6, o = idx & 63;
        *(u64*)&yb[idx] = *(const u64*)&sY[ww * YPAD + o];
    }
}

extern "C" void kernel_launch(void* const* d_in, const int* in_sizes, int n_in,
                              void* d_out, int out_size) {
    const float* x  = (const float*)d_in[0];
    const float* wr = (const float*)d_in[1];
    const float* wi = (const float*)d_in[2];
    float* y = (float*)d_out;

    fusedAT<<<2048, 256>>>(x, wr, wi);   // 1024 A-blocks + 1024 transpose blocks
    stageB<<<B * MD * 2, 256>>>();
    stageC<<<MD * MD * 2, 256>>>();
    stageD<<<B * MD * 2, 256>>>();
    stageE<<<B * Hh, 128>>>(y);
}

// round 16
// speedup vs baseline: 1.0925x; 1.0925x over previous
#include <cuda_runtime.h>
#include <math.h>

#define B   16
#define Hh  128
#define Ww  128
#define CI  64
#define CO  64
#define MD  16
#define THETA 0.04908738521234052f   // 2*pi/128

typedef unsigned long long u64;

__device__ __forceinline__ u64 pk(float lo, float hi) {
    u64 r; asm("mov.b64 %0, {%1,%2};" : "=l"(r) : "f"(lo), "f"(hi)); return r;
}
__device__ __forceinline__ u64 fma2(u64 a, u64 b, u64 c) {
    u64 d; asm("fma.rn.f32x2 %0, %1, %2, %3;" : "=l"(d) : "l"(a), "l"(b), "l"(c)); return d;
}
__device__ __forceinline__ u64 add2(u64 a, u64 b) {
    u64 d; asm("add.rn.f32x2 %0, %1, %2;" : "=l"(d) : "l"(a), "l"(b)); return d;
}
#define SGN2 0x8000000080000000ULL

// ---- scratch (device globals; allocation-free). 16B aligned ----
static __device__ __align__(16) float g_Ax[B*MD*Hh*CI];     // [b][kx][h][i]
static __device__ __align__(16) float g_Ay[B*MD*Hh*CI];
static __device__ __align__(16) float g_Xx[MD*MD*B*CI];     // [m][b][i]
static __device__ __align__(16) float g_Xy[MD*MD*B*CI];
static __device__ __align__(16) float g_Wr[MD*MD*CI*CO];    // [m][i*64+o]
static __device__ __align__(16) float g_Wi[MD*MD*CI*CO];
static __device__ __align__(16) float g_Ox[B*MD*MD*CO];     // [b][kx][ky][o]
static __device__ __align__(16) float g_Oy[B*MD*MD*CO];
static __device__ __align__(16) float g_Gx[B*Hh*MD*CO];     // [b][h][kx][o]
static __device__ __align__(16) float g_Gy[B*Hh*MD*CO];

// ============ fused stage A (radix-2, fused twiddle LDS.128) + weight transpose ============
__global__ void __launch_bounds__(256) fusedAT(const float* __restrict__ x,
                                               const float* __restrict__ wr,
                                               const float* __restrict__ wi) {
    __shared__ __align__(16) float pool[8192];       // 32 KB
    __shared__ __align__(16) ulonglong2 sbt[128];    // {(c,c),(s,s)} 2 KB
    int tid = threadIdx.x;

    if (blockIdx.x >= 1024) {
        // ---- weight transpose tile: 32 m x 32 io ----
        int t   = blockIdx.x - 1024;
        int bm  = t & 7;
        int bio = t >> 3;
        int tx  = tid & 31;
        int ty  = tid >> 5;                 // 0..7
        float* sr = pool;                   // [32][33]
        float* si = pool + 1056;
#pragma unroll
        for (int r = 0; r < 4; ++r) {
            int iol = ty + r * 8;
            size_t g = (size_t)(bio * 32 + iol) * 256 + bm * 32 + tx;
            sr[iol * 33 + tx] = wr[g];
            si[iol * 33 + tx] = wi[g];
        }
        __syncthreads();
#pragma unroll
        for (int r = 0; r < 4; ++r) {
            int ml = ty + r * 8;
            size_t dst = (size_t)(bm * 32 + ml) * 4096 + bio * 32 + tx;
            g_Wr[dst] = sr[tx * 33 + ml];
            g_Wi[dst] = si[tx * 33 + ml];
        }
        return;
    }

    // ---- stage A: A[kx] = sum_{w'<64} u_{par(kx)}[w'] e^{-i kx w' th} ----
    if (tid < 128) {
        float s, c;
        sincosf((float)tid * THETA, &s, &c);
        ulonglong2 t;
        t.x = pk(c, c);
        t.y = pk(s, s);
        sbt[tid] = t;
    }
    int b  = blockIdx.x >> 6;
    int hp = blockIdx.x & 63;
    int h0 = hp * 2;
    int ipair = tid & 31, kq = tid >> 5;   // kx = kq, kq+8 (same parity); warp-uniform kq
    int i0 = 2 * ipair;
    int kxa = kq, kxb = kq + 8;
    int du = (kq & 1) * 2048;              // odd kx -> um region
    u64 reA0=0, imA0=0, reB0=0, imB0=0;    // row0: kxa, kxb
    u64 reA1=0, imA1=0, reB1=0, imB1=0;    // row1

    for (int wc = 0; wc < 2; ++wc) {
        __syncthreads();
#pragma unroll
        for (int r = 0; r < 2; ++r) {
            const ulonglong2* src = (const ulonglong2*)(x + ((size_t)(b * Hh + h0 + r) * Ww + wc * 32) * CI);
            ulonglong2* dp = (ulonglong2*)&pool[r * 4096];
            ulonglong2* dm = (ulonglong2*)&pool[r * 4096 + 2048];
            for (int l = tid; l < 512; l += 256) {
                ulonglong2 a = src[l];            // x[w']
                ulonglong2 c = src[l + 1024];     // x[w'+64]
                ulonglong2 p, m;
                p.x = add2(a.x, c.x);         p.y = add2(a.y, c.y);
                m.x = add2(a.x, c.x ^ SGN2);  m.y = add2(a.y, c.y ^ SGN2);
                dp[l] = p;
                dm[l] = m;
            }
        }
        __syncthreads();
        int ida = (kxa * (wc * 32)) & 127;
        int idb = (kxb * (wc * 32)) & 127;
#pragma unroll 8
        for (int wl = 0; wl < 32; ++wl) {
            u64 v0 = *(const u64*)&pool[du + wl * 64 + i0];
            u64 v1 = *(const u64*)&pool[4096 + du + wl * 64 + i0];
            ulonglong2 ta = sbt[ida];
            ulonglong2 tb = sbt[idb];
            ida = (ida + kxa) & 127;
            idb = (idb + kxb) & 127;
            reA0 = fma2(v0, ta.x, reA0);  imA0 = fma2(v0, ta.y, imA0);
            reA1 = fma2(v1, ta.x, reA1);  imA1 = fma2(v1, ta.y, imA1);
            reB0 = fma2(v0, tb.x, reB0);  imB0 = fma2(v0, tb.y, imB0);
            reB1 = fma2(v1, tb.x, reB1);  imB1 = fma2(v1, tb.y, imB1);
        }
    }
    size_t baseA0 = ((size_t)(b * MD + kxa) * Hh + h0    ) * CI;
    size_t baseA1 = ((size_t)(b * MD + kxa) * Hh + h0 + 1) * CI;
    size_t baseB0 = ((size_t)(b * MD + kxb) * Hh + h0    ) * CI;
    size_t baseB1 = ((size_t)(b * MD + kxb) * Hh + h0 + 1) * CI;
    *(u64*)&g_Ax[baseA0 + i0] = reA0;  *(u64*)&g_Ay[baseA0 + i0] = imA0 ^ SGN2;
    *(u64*)&g_Ax[baseA1 + i0] = reA1;  *(u64*)&g_Ay[baseA1 + i0] = imA1 ^ SGN2;
    *(u64*)&g_Ax[baseB0 + i0] = reB0;  *(u64*)&g_Ay[baseB0 + i0] = imB0 ^ SGN2;
    *(u64*)&g_Ax[baseB1 + i0] = reB1;  *(u64*)&g_Ay[baseB1 + i0] = imB1 ^ SGN2;
}

// ============ stage B (radix-2, fused twiddle LDS.128): X[m][b][i] = sum_h A e^{-i ky h th} ============
__global__ void __launch_bounds__(256) stageB() {
    __shared__ __align__(16) float bxp[32 * 64];   // u+ (re) 8 KB
    __shared__ __align__(16) float bxm[32 * 64];   // u- (re)
    __shared__ __align__(16) float byp[32 * 64];   // u+ (im)
    __shared__ __align__(16) float bym[32 * 64];   // u- (im)
    __shared__ __align__(16) ulonglong2 sbt[128];  // {(c,c),(s,s)}
    int b  = blockIdx.x >> 4;
    int kx = blockIdx.x & 15;
    int tid = threadIdx.x;
    if (tid < 128) {
        float s, c;
        sincosf((float)tid * THETA, &s, &c);
        ulonglong2 t;
        t.x = pk(c, c);
        t.y = pk(s, s);
        sbt[tid] = t;
    }
    int ipair = tid & 31, kyg = tid >> 5;   // ky = kyg, kyg+8 (same parity); warp-uniform
    int i0 = 2 * ipair;
    int ky0 = kyg, ky1 = kyg + 8;
    int par = kyg & 1;
    u64 P0=0,Q0=0,R0=0,S0=0, P1=0,Q1=0,R1=0,S1=0;
    const ulonglong2* Abx = (const ulonglong2*)(g_Ax + (size_t)(b * MD + kx) * Hh * CI);
    const ulonglong2* Aby = (const ulonglong2*)(g_Ay + (size_t)(b * MD + kx) * Hh * CI);

    for (int hc = 0; hc < 2; ++hc) {
        __syncthreads();
        for (int l = tid; l < 512; l += 256) {
            int row = l >> 4, q = l & 15;
            int glo = (hc * 32 + row) * 16 + q;
            int ghi = (hc * 32 + row + 64) * 16 + q;
            ulonglong2 ax = Abx[glo], cx = Abx[ghi];
            ulonglong2 ay = Aby[glo], cy = Aby[ghi];
            ulonglong2 t;
            t.x = add2(ax.x, cx.x);        t.y = add2(ax.y, cx.y);
            ((ulonglong2*)bxp)[l] = t;
            t.x = add2(ax.x, cx.x ^ SGN2); t.y = add2(ax.y, cx.y ^ SGN2);
            ((ulonglong2*)bxm)[l] = t;
            t.x = add2(ay.x, cy.x);        t.y = add2(ay.y, cy.y);
            ((ulonglong2*)byp)[l] = t;
            t.x = add2(ay.x, cy.x ^ SGN2); t.y = add2(ay.y, cy.y ^ SGN2);
            ((ulonglong2*)bym)[l] = t;
        }
        __syncthreads();
        const float* bx = par ? bxm : bxp;
        const float* by = par ? bym : byp;
        int idx0 = (ky0 * (hc * 32)) & 127;
        int idx1 = (ky1 * (hc * 32)) & 127;
#pragma unroll 8
        for (int hl = 0; hl < 32; ++hl) {
            u64 ar = *(const u64*)&bx[hl * 64 + i0];
            u64 ai = *(const u64*)&by[hl * 64 + i0];
            ulonglong2 t0 = sbt[idx0];
            ulonglong2 t1 = sbt[idx1];
            idx0 = (idx0 + ky0) & 127;
            idx1 = (idx1 + ky1) & 127;
            P0 = fma2(ar, t0.x, P0);  Q0 = fma2(ai, t0.y, Q0);
            R0 = fma2(ai, t0.x, R0);  S0 = fma2(ar, t0.y, S0);
            P1 = fma2(ar, t1.x, P1);  Q1 = fma2(ai, t1.y, Q1);
            R1 = fma2(ai, t1.x, R1);  S1 = fma2(ar, t1.y, S1);
        }
    }
    // re = P + Q ; im = R - S
    size_t b0 = ((size_t)(ky0 * MD + kx) * B + b) * CI;
    size_t b1 = ((size_t)(ky1 * MD + kx) * B + b) * CI;
    *(u64*)&g_Xx[b0 + i0] = add2(P0, Q0);
    *(u64*)&g_Xy[b0 + i0] = add2(R0, S0 ^ SGN2);
    *(u64*)&g_Xx[b1 + i0] = add2(P1, Q1);
    *(u64*)&g_Xy[b1 + i0] = add2(R1, S1 ^ SGN2);
}

// ============ stage C: O[b][kx][ky][o] = sum_i X[m][b][i]*W[m][i][o] ============
__global__ void __launch_bounds__(256) stageC() {
    __shared__ __align__(16) float sWr[CI * CO];
    __shared__ __align__(16) float sWi[CI * CO];
    __shared__ __align__(16) u64 sXx[B * CI];
    __shared__ __align__(16) u64 sXn[B * CI];
    int m = blockIdx.x;
    int kx = m & 15, ky = m >> 4;
    int tid = threadIdx.x;
    const float4* Wr4 = (const float4*)(g_Wr + (size_t)m * 4096);
    const float4* Wi4 = (const float4*)(g_Wi + (size_t)m * 4096);
    for (int l = tid; l < 1024; l += 256) {
        ((float4*)sWr)[l] = Wr4[l];
        ((float4*)sWi)[l] = Wi4[l];
    }
    for (int l = tid; l < 1024; l += 256) {
        float vx = g_Xx[m * 1024 + l];
        float vy = g_Xy[m * 1024 + l];
        sXx[l] = pk(vx, vx);
        sXn[l] = pk(-vy, -vy);
    }
    __syncthreads();
    int oq = tid & 15;
    int b  = tid >> 4;
    u64 P0=0,P1=0,Q0=0,Q1=0,R0=0,R1=0,S0=0,S1=0;
    const u64* xp = &sXx[b * 64];
    const u64* np = &sXn[b * 64];
#pragma unroll 8
    for (int i = 0; i < CI; ++i) {
        ulonglong2 wr2 = *(const ulonglong2*)&sWr[i * 64 + 4 * oq];
        ulonglong2 wi2 = *(const ulonglong2*)&sWi[i * 64 + 4 * oq];
        u64 xv = xp[i], nv = np[i];
        P0 = fma2(xv, wr2.x, P0);  P1 = fma2(xv, wr2.y, P1);
        Q0 = fma2(nv, wi2.x, Q0);  Q1 = fma2(nv, wi2.y, Q1);
        R0 = fma2(xv, wi2.x, R0);  R1 = fma2(xv, wi2.y, R1);
        S0 = fma2(nv, wr2.x, S0);  S1 = fma2(nv, wr2.y, S1);
    }
    size_t base = ((size_t)(b * MD + kx) * MD + ky) * CO + 4 * oq;
    *(u64*)&g_Ox[base    ] = add2(P0, Q0);
    *(u64*)&g_Ox[base + 2] = add2(P1, Q1);
    *(u64*)&g_Oy[base    ] = add2(R0, S0 ^ SGN2);
    *(u64*)&g_Oy[base + 2] = add2(R1, S1 ^ SGN2);
}

// ============ stage D (radix-2, fused twiddle LDS.128): G[h'] = Se+So, G[h'+64] = Se-So ============
__global__ void __launch_bounds__(256, 4) stageD() {
    __shared__ __align__(16) float sOx[MD * CO];
    __shared__ __align__(16) float sOy[MD * CO];
    __shared__ __align__(16) ulonglong2 sT[MD * 32];   // {(c,c),(s,s)} [ky][hl]
    int half = blockIdx.x & 1;
    int kx   = (blockIdx.x >> 1) & 15;
    int b    = blockIdx.x >> 5;
    int hb   = half * 32;                        // h' base (h' < 64)
    int tid  = threadIdx.x;
    for (int l = tid; l < 512; l += 256) {
        int ky = l >> 5, hl = l & 31;
        float s, c;
        sincosf((float)((ky * (hb + hl)) & 127) * THETA, &s, &c);
        ulonglong2 t;
        t.x = pk(c, c);
        t.y = pk(s, s);
        sT[l] = t;
    }
    const float* Osx = g_Ox + (size_t)(b * MD + kx) * MD * CO;
    const float* Osy = g_Oy + (size_t)(b * MD + kx) * MD * CO;
    for (int l = tid; l < 256; l += 256) {
        ((float4*)sOx)[l] = ((const float4*)Osx)[l];
        ((float4*)sOy)[l] = ((const float4*)Osy)[l];
    }
    __syncthreads();

    int oq = tid & 15;    // o = 4*oq (2 pairs)
    int hg = tid >> 4;    // h' = hb + 2*hg + j
    u64 reE[2][2]={{0,0},{0,0}}, imE[2][2]={{0,0},{0,0}};
    u64 reO[2][2]={{0,0},{0,0}}, imO[2][2]={{0,0},{0,0}};
#pragma unroll
    for (int ky = 0; ky < MD; ++ky) {
        ulonglong2 vx = *(const ulonglong2*)&sOx[ky * 64 + 4 * oq];
        ulonglong2 vy = *(const ulonglong2*)&sOy[ky * 64 + 4 * oq];
        u64 vy0n = vy.x ^ SGN2;
        u64 vy1n = vy.y ^ SGN2;
#pragma unroll
        for (int j = 0; j < 2; ++j) {
            int hl = hg * 2 + j;
            ulonglong2 t = sT[ky * 32 + hl];
            u64 cc = t.x, ss = t.y;
            if ((ky & 1) == 0) {
                reE[j][0] = fma2(vx.x, cc, reE[j][0]);  reE[j][0] = fma2(vy0n, ss, reE[j][0]);
                reE[j][1] = fma2(vx.y, cc, reE[j][1]);  reE[j][1] = fma2(vy1n, ss, reE[j][1]);
                imE[j][0] = fma2(vx.x, ss, imE[j][0]);  imE[j][0] = fma2(vy.x, cc, imE[j][0]);
                imE[j][1] = fma2(vx.y, ss, imE[j][1]);  imE[j][1] = fma2(vy.y, cc, imE[j][1]);
            } else {
                reO[j][0] = fma2(vx.x, cc, reO[j][0]);  reO[j][0] = fma2(vy0n, ss, reO[j][0]);
                reO[j][1] = fma2(vx.y, cc, reO[j][1]);  reO[j][1] = fma2(vy1n, ss, reO[j][1]);
                imO[j][0] = fma2(vx.x, ss, imO[j][0]);  imO[j][0] = fma2(vy.x, cc, imO[j][0]);
                imO[j][1] = fma2(vx.y, ss, imO[j][1]);  imO[j][1] = fma2(vy.y, cc, imO[j][1]);
            }
        }
    }
#pragma unroll
    for (int j = 0; j < 2; ++j) {
        int h = hb + hg * 2 + j;
        size_t b0 = ((size_t)(b * Hh + h     ) * MD + kx) * CO + 4 * oq;
        size_t b1 = ((size_t)(b * Hh + h + 64) * MD + kx) * CO + 4 * oq;
        *(u64*)&g_Gx[b0    ] = add2(reE[j][0], reO[j][0]);
        *(u64*)&g_Gx[b0 + 2] = add2(reE[j][1], reO[j][1]);
        *(u64*)&g_Gy[b0    ] = add2(imE[j][0], imO[j][0]);
        *(u64*)&g_Gy[b0 + 2] = add2(imE[j][1], imO[j][1]);
        *(u64*)&g_Gx[b1    ] = add2(reE[j][0], reO[j][0] ^ SGN2);
        *(u64*)&g_Gx[b1 + 2] = add2(reE[j][1], reO[j][1] ^ SGN2);
        *(u64*)&g_Gy[b1    ] = add2(imE[j][0], imO[j][0] ^ SGN2);
        *(u64*)&g_Gy[b1 + 2] = add2(imE[j][1], imO[j][1] ^ SGN2);
    }
}

// ============ stage E v3 (radix-2, G in regs, direct coalesced STG) ============
// Thread = (o-pair lane 32) x (w-group 4). No sY staging; 16 KB twiddle table.
__global__ void __launch_bounds__(128) stageE(float* __restrict__ y) {
    __shared__ __align__(16) ulonglong2 sT[MD * 64];   // {(fc,fc),(fs,fs)} [kx][w'] 16 KB
    int b = blockIdx.x >> 7, h = blockIdx.x & 127;
    int tid = threadIdx.x;
    const float SC = 1.0f / 16384.0f;                  // ortho fwd*inv = 1/(H*W)
    for (int l = tid; l < MD * 64; l += 128) {
        int kx = l >> 6, wl = l & 63;
        ulonglong2 t;
        if (kx == 0) {
            t.x = pk(SC, SC);
            t.y = 0;
        } else {
            float s, c;
            sincosf((float)((kx * wl) & 127) * THETA, &s, &c);
            float fc = 2.0f * SC * c, fs = -2.0f * SC * s;
            t.x = pk(fc, fc);
            t.y = pk(fs, fs);
        }
        sT[l] = t;
    }
    // G into registers: coalesced LDG.64 (lane = o-pair)
    int op = tid & 31;        // o = 2*op
    int wg = tid >> 5;        // w' = wg*16 + j  (warp-uniform)
    size_t gbase = (size_t)(b * Hh + h) * MD * CO + 2 * op;
    u64 Gx[16], Gy[16];
#pragma unroll
    for (int kx = 0; kx < MD; ++kx) {
        Gx[kx] = *(const u64*)&g_Gx[gbase + kx * 64];
        Gy[kx] = *(const u64*)&g_Gy[gbase + kx * 64];
    }
    __syncthreads();

    float* yb = y + (size_t)(b * Hh + h) * Ww * CO;
#pragma unroll 2
    for (int j = 0; j < 16; ++j) {
        int wl = wg * 16 + j;
        u64 ae = 0, ao = 0;
#pragma unroll
        for (int kx = 0; kx < MD; kx += 2) {
            ulonglong2 te = sT[kx * 64 + wl];          // broadcast
            ulonglong2 to = sT[(kx + 1) * 64 + wl];    // broadcast
            ae = fma2(Gx[kx    ], te.x, ae);  ae = fma2(Gy[kx    ], te.y, ae);
            ao = fma2(Gx[kx + 1], to.x, ao);  ao = fma2(Gy[kx + 1], to.y, ao);
        }
        *(u64*)&yb[(size_t)wl * CO + 2 * op]        = add2(ae, ao);
        *(u64*)&yb[(size_t)(wl + 64) * CO + 2 * op] = add2(ae, ao ^ SGN2);
    }
}

extern "C" void kernel_launch(void* const* d_in, const int* in_sizes, int n_in,
                              void* d_out, int out_size) {
    const float* x  = (const float*)d_in[0];
    const float* wr = (const float*)d_in[1];
    const float* wi = (const float*)d_in[2];
    float* y = (float*)d_out;

    fusedAT<<<2048, 256>>>(x, wr, wi);   // 1024 A-blocks + 1024 transpose blocks
    stageB<<<B * MD, 256>>>();
    stageC<<<MD * MD, 256>>>();
    stageD<<<B * MD * 2, 256>>>();
    stageE<<<B * Hh, 128>>>(y);
}